// round 6
// baseline (speedup 1.0000x reference)
#include <cuda_runtime.h>

// DMTSkeletonize: exact squared-EDT with adaptive candidate window (bit-exact:
// excluding j with (i-j)^2 >= running-min can't change the min since f >= 0),
// plus a z-marching fused 3x3x3 local-max skeleton kernel on d^2.
//
// Shapes: img [4,1,160,160,160] fp32. B=4, D=H=W=160.

#define WW    160
#define HWSZ  25600      // H*W
#define DHWSZ 4096000    // D*H*W
#define NTOT  16384000   // B*D*H*W
#define FINF  1e12f
#define NEGINF (-3.0e38f)

// Scratch (device globals — no allocation anywhere, per harness rules)
__device__ float g_A[NTOT];
__device__ float g_B[NTOT];

// ---------------------------------------------------------------------------
// EDT 1D pass: out[line][i] = min_j fl(f[line][j] + (i-j)^2)
// MODE 0: lines along x (contiguous); input = img binarized; writes g_A
// MODE 1: lines along y (stride W);   g_A -> g_B
// MODE 2: lines along z (stride H*W); g_B -> g_A
// 512 threads, 32 lines/block; thread = (line, segment-of-10); adaptive
// outward scan, two independent outputs in flight per thread (ILP=2).
// ---------------------------------------------------------------------------
template <int MODE>
__global__ __launch_bounds__(512) void edt_pass_kernel(const float* __restrict__ img)
{
    __shared__ float fsh[32][161];  // pad: conflict-free transposed access

    const float* __restrict__ in  = (MODE == 0) ? img : (MODE == 1 ? g_A : g_B);
    float* __restrict__       out = (MODE == 1) ? g_B : g_A;

    const int tid = threadIdx.x;
    const int bid = blockIdx.x;

    long base;
    int stride;
    if (MODE == 0) {
        base = (long)bid * (32 * 160);
        stride = 1;
    } else if (MODE == 1) {
        int p  = bid / 5;            // p = b*160 + z
        int x0 = (bid % 5) * 32;
        base = (long)p * HWSZ + x0;
        stride = WW;
    } else {
        int p  = bid / 5;            // p = b*160 + y
        int x0 = (bid % 5) * 32;
        int b = p / 160, y = p - b * 160;
        base = (long)b * DHWSZ + (long)y * WW + x0;
        stride = HWSZ;
    }

    // ---- load tile into shared (coalesced) ----
    if (MODE == 0) {
        for (int idx = tid; idx < 32 * 160; idx += 512) {
            int l = idx / 160;
            int j = idx - l * 160;
            float v = in[base + idx];
            fsh[l][j] = (v > 0.5f) ? 0.0f : FINF;     // binarize + invert
        }
    } else {
        for (int idx = tid; idx < 32 * 160; idx += 512) {
            int j = idx >> 5;
            int l = idx & 31;
            fsh[l][j] = in[base + (long)j * stride + l];
        }
    }
    __syncthreads();

    // ---- adaptive-window min-plus transform, 2 outputs in flight ----
    const int l = tid >> 4;          // line 0..31
    const int s = tid & 15;          // segment 0..15 (10 outputs each)
    const float* __restrict__ f = fsh[l];

    float res[10];
#pragma unroll 1
    for (int o = 0; o < 5; o++) {
        const int i1 = s * 10 + o;
        const int i2 = i1 + 5;
        float a1 = f[i1];            // j = i term: fl(f+0) = f exactly
        float a2 = f[i2];
#pragma unroll 1
        for (int k = 1; k < 160; k++) {
            const float kk = (float)(k * k);        // exact in fp32
            const bool g1 = kk < a1;
            const bool g2 = kk < a2;
            if (!(g1 | g2)) break;
            if (g1) {
                int jn = i1 - k, jp = i1 + k;
                if (jn >= 0)  a1 = fminf(a1, kk + f[jn]);  // 1 rounding = ref
                if (jp < 160) a1 = fminf(a1, kk + f[jp]);
            }
            if (g2) {
                int jn = i2 - k, jp = i2 + k;
                if (jn >= 0)  a2 = fminf(a2, kk + f[jn]);
                if (jp < 160) a2 = fminf(a2, kk + f[jp]);
            }
        }
        res[o] = a1;
        res[o + 5] = a2;
    }

    __syncthreads();   // all reads of fsh done before overwrite
#pragma unroll
    for (int o = 0; o < 10; o++) fsh[l][s * 10 + o] = res[o];
    __syncthreads();

    // ---- coalesced store ----
    if (MODE == 0) {
        for (int idx = tid; idx < 32 * 160; idx += 512) {
            int ll = idx / 160;
            int j  = idx - ll * 160;
            out[base + idx] = fsh[ll][j];
        }
    } else {
        for (int idx = tid; idx < 32 * 160; idx += 512) {
            int j  = idx >> 5;
            int ll = idx & 31;
            out[base + (long)j * stride + ll] = fsh[ll][j];
        }
    }
}

// ---------------------------------------------------------------------------
// Fused 3x3x3 neighborhood max + skeleton + multiply, z-marching version.
// Block: 256 threads = (x=32, y=8), tile 32x32 in xy (each thread 4 y-strips),
// marches 40 z-slices with double-buffered 34x34 halo slices in shared.
// grid = (5, 5, 16): xy tiles x (batch*4 + zchunk).
// ---------------------------------------------------------------------------
__global__ __launch_bounds__(256) void skel_kernel(const float* __restrict__ img,
                                                   float* __restrict__ out)
{
    __shared__ float sA[2][34][36];   // pad 36: conflict-free rows

    const int tid = threadIdx.x;
    const int tx  = tid & 31;
    const int ty  = tid >> 5;                // 0..7
    const int x0  = blockIdx.x * 32;
    const int y0  = blockIdx.y * 32;
    const int b   = blockIdx.z >> 2;
    const int z0  = (blockIdx.z & 3) * 40;
    const long gbase = (long)b * DHWSZ;
    const float* __restrict__ A = g_A + gbase;

    float xa[4], xb[4];       // xy-max at slice zs-2, zs-1
    float ch[4];              // center value at slice zs-1
#pragma unroll
    for (int s_ = 0; s_ < 4; s_++) { xa[s_] = NEGINF; xb[s_] = NEGINF; ch[s_] = 0.0f; }

    // march slices zs = z0-1 .. z0+40
#pragma unroll 1
    for (int it = 0; it < 42; it++) {
        const int zs = z0 - 1 + it;
        const int buf = it & 1;

        // load slice zs (34x34 halo, OOB = -inf)
        const bool zok = (zs >= 0) & (zs < 160);
        const float* __restrict__ S = A + (long)zs * HWSZ;
        for (int idx = tid; idx < 34 * 34; idx += 256) {
            int hy = idx / 34;
            int hx = idx - hy * 34;
            int gx = x0 + hx - 1, gy = y0 + hy - 1;
            float v = NEGINF;
            if (zok && gx >= 0 && gx < 160 && gy >= 0 && gy < 160)
                v = S[gy * WW + gx];
            sA[buf][hy][hx] = v;
        }
        __syncthreads();

        // compute 3x3 xy-max + center for this slice, emit output for zs-1
#pragma unroll
        for (int s_ = 0; s_ < 4; s_++) {
            const int hy = ty + 8 * s_ + 1;
            float m0 = fmaxf(fmaxf(sA[buf][hy - 1][tx], sA[buf][hy - 1][tx + 1]), sA[buf][hy - 1][tx + 2]);
            float c  = sA[buf][hy][tx + 1];
            float m1 = fmaxf(fmaxf(sA[buf][hy][tx], c), sA[buf][hy][tx + 2]);
            float m2 = fmaxf(fmaxf(sA[buf][hy + 1][tx], sA[buf][hy + 1][tx + 1]), sA[buf][hy + 1][tx + 2]);
            float xn = fmaxf(fmaxf(m0, m1), m2);

            if (it >= 2) {      // output at zo = zs-1 in [z0, z0+40)
                float m = fmaxf(fmaxf(xa[s_], xb[s_]), xn);
                float cc = ch[s_];
                long gi = gbase + (long)(zs - 1) * HWSZ + (y0 + ty + 8 * s_) * WW + (x0 + tx);
                out[gi] = (cc >= m && cc > 0.0f) ? img[gi] : 0.0f;
            }
            xa[s_] = xb[s_];
            xb[s_] = xn;
            ch[s_] = c;
        }
        // no second barrier needed: double buffer; a thread's load of buf at
        // it+2 is ordered after sync#(it+1), which is after ALL threads'
        // compute(it) reads of buf.
    }
}

// ---------------------------------------------------------------------------
extern "C" void kernel_launch(void* const* d_in, const int* in_sizes, int n_in,
                              void* d_out, int out_size)
{
    const float* img = (const float*)d_in[0];
    float* out = (float*)d_out;

    // EDT: x -> y -> z  (g_A holds final d^2)
    edt_pass_kernel<0><<<3200, 512>>>(img);
    edt_pass_kernel<1><<<3200, 512>>>(nullptr);
    edt_pass_kernel<2><<<3200, 512>>>(nullptr);

    // Fused 3x3x3 max + skeleton + multiply (z-marching)
    skel_kernel<<<dim3(5, 5, 16), 256>>>(img, out);
}